// round 7
// baseline (speedup 1.0000x reference)
#include <cuda_runtime.h>
#include <cstdint>

// VQ-VAE vector quantizer for GB300 — single kernel, packed f32x2 FMA,
// code-pair lane packing (no broadcast-dup MOVs in the hot loop).
// latents: [B=32, D=64, H=64, W=64] fp32, emb_weight: [K=512, D=64] fp32.
//
// Precision: per-(pixel,code) fp32 rounding chain replicated EXACTLY
// (R3 measured rel_err 0.0 with this chain):
//   sumw_k: unfused fl(w*w), ascending d
//   sumf  : unfused fl(f*f), ascending d
//   s_k   : sequential FMA chain ascending d (fma.rn.f32x2 is IEEE per lane;
//           lanes carry two CODES, so each code's chain order is unchanged)
//   dist  = fl( fl(sumf + sumw_k) - fl(2*s_k) ); strict-<, ascending-k argmin
//   q_st  = fl( f + fl(q - f) )

#define KCODES 512
#define DDIM   64
#define HW     4096
#define NPIX   131072
#define BLOCK  256
#define NELEM  8388608
#define GRID   (NPIX / BLOCK)          // 512 blocks, 1 pixel/thread

__device__ double   g_loss_sum   = 0.0;
__device__ unsigned g_done_count = 0u;

#define PACK2(r, lo, hi) \
    asm("mov.b64 %0, {%1, %2};" : "=l"(r) : "r"(lo), "r"(hi))
#define UNPACK2(lo, hi, r) \
    asm("mov.b64 {%0, %1}, %2;" : "=r"(lo), "=r"(hi) : "l"(r))
#define FMA2(acc, a, b) \
    asm("fma.rn.f32x2 %0, %1, %2, %3;" : "=l"(acc) : "l"(a), "l"(b), "l"(acc))

__global__ void __launch_bounds__(BLOCK, 1) vq_kernel(
    const float* __restrict__ lat,
    const float* __restrict__ w,
    float* __restrict__ out,
    int loss_idx)
{
    extern __shared__ char smem_raw[];
    // Interleaved codebook: pair-row k2 (512 B) holds, for d = 0..63,
    // the float pair (w[2k2][d], w[2k2+1][d]).  128 KB total.
    float*  spair = reinterpret_cast<float*>(smem_raw);
    float*  ssumw = reinterpret_cast<float*>(smem_raw + KCODES * DDIM * 4);  // 512 floats
    double* sred  = reinterpret_cast<double*>(smem_raw + KCODES * DDIM * 4 + KCODES * 4);

    const int tid = threadIdx.x;

    // ---- build interleaved codebook in smem (coalesced LDG, one-time) ----
    for (int i = tid; i < KCODES * DDIM; i += BLOCK) {
        int k = i >> 6;          // code
        int d = i & 63;          // dim
        spair[(k >> 1) * 128 + d * 2 + (k & 1)] = w[i];
    }
    // ---- per-code sumw, reference rounding (gmem is L2-hot) ----
#pragma unroll
    for (int c = 0; c < KCODES / BLOCK; ++c) {
        int k = tid + c * BLOCK;
        const float* wr = w + k * DDIM;
        float acc = 0.0f;
#pragma unroll
        for (int d = 0; d < DDIM; ++d)
            acc = __fadd_rn(acc, __fmul_rn(wr[d], wr[d]));
        ssumw[k] = acc;
    }
    __syncthreads();

    // ---- load this thread's pixel, pack (f[d], f[d]) ----
    const int n  = blockIdx.x * BLOCK + tid;
    const int b  = n >> 12;
    const int hw = n & (HW - 1);
    const float* lp = lat + (size_t)b * (DDIM * HW) + hw;

    uint64_t fdup[DDIM];
    float sumf = 0.0f;
#pragma unroll
    for (int d = 0; d < DDIM; ++d) {
        float v = lp[(size_t)d * HW];                 // coalesced within warp
        uint32_t vb = __float_as_uint(v);
        PACK2(fdup[d], vb, vb);
        sumf = __fadd_rn(sumf, __fmul_rn(v, v));      // unfused, ascending d
    }

    // ---- argmin: 2 code-pairs (4 codes) per iteration, 2 indep FMA2 chains ----
    float best = 3.4e38f;
    int   bi   = 0;
    const ulonglong2* pv = reinterpret_cast<const ulonglong2*>(spair);

#pragma unroll 1
    for (int k2 = 0; k2 < KCODES / 2; k2 += 2) {
        const ulonglong2* rA = pv + (size_t)k2 * 32;        // pair k2   (codes 2k2, 2k2+1)
        const ulonglong2* rB = rA + 32;                     // pair k2+1 (codes 2k2+2, 2k2+3)
        uint64_t accA, accB;
        PACK2(accA, 0u, 0u);
        PACK2(accB, 0u, 0u);
#pragma unroll
        for (int j = 0; j < 32; ++j) {
            ulonglong2 a  = rA[j];    // (d=2j, d=2j+1) packed operands, LDS.128 broadcast
            ulonglong2 bb = rB[j];
            FMA2(accA, fdup[2 * j],     a.x);
            FMA2(accB, fdup[2 * j],     bb.x);
            FMA2(accA, fdup[2 * j + 1], a.y);
            FMA2(accB, fdup[2 * j + 1], bb.y);
        }
        uint32_t lo, hi;
        UNPACK2(lo, hi, accA);
        float s0 = __uint_as_float(lo), s1 = __uint_as_float(hi);
        UNPACK2(lo, hi, accB);
        float s2 = __uint_as_float(lo), s3 = __uint_as_float(hi);

        const int kb = 2 * k2;
        float d0 = __fsub_rn(__fadd_rn(sumf, ssumw[kb + 0]), __fmul_rn(2.0f, s0));
        float d1 = __fsub_rn(__fadd_rn(sumf, ssumw[kb + 1]), __fmul_rn(2.0f, s1));
        float d2 = __fsub_rn(__fadd_rn(sumf, ssumw[kb + 2]), __fmul_rn(2.0f, s2));
        float d3 = __fsub_rn(__fadd_rn(sumf, ssumw[kb + 3]), __fmul_rn(2.0f, s3));
        if (d0 < best) { best = d0; bi = kb + 0; }          // ascending k, strict <
        if (d1 < best) { best = d1; bi = kb + 1; }
        if (d2 < best) { best = d2; bi = kb + 2; }
        if (d3 < best) { best = d3; bi = kb + 3; }
    }

    // ---- gather winner, straight-through output, loss ----
    double lloss = 0.0;
    {
        float* op = out + (size_t)b * (DDIM * HW) + hw;
        const float* q = spair + (bi >> 1) * 128 + (bi & 1);   // stride-2 reads
#pragma unroll
        for (int d = 0; d < DDIM; ++d) {
            uint32_t flo, fhi;
            UNPACK2(flo, fhi, fdup[d]);
            float fd   = __uint_as_float(flo);
            float qd   = q[2 * d];
            float diff = __fsub_rn(qd, fd);
            op[(size_t)d * HW] = __fadd_rn(fd, diff);          // fl(lat + fl(q - lat))
            lloss += (double)diff * (double)diff;
        }
    }

    // ---- block loss reduction -> one atomicAdd per block ----
#pragma unroll
    for (int off = 16; off > 0; off >>= 1)
        lloss += __shfl_down_sync(0xFFFFFFFFu, lloss, off);
    int lane = tid & 31;
    int wid  = tid >> 5;
    if (lane == 0) sred[wid] = lloss;
    __syncthreads();

    // ---- last-block finalize ----
    if (tid == 0) {
        double t = 0.0;
#pragma unroll
        for (int i = 0; i < BLOCK / 32; ++i) t += sred[i];
        atomicAdd(&g_loss_sum, t);
        __threadfence();
        unsigned prev = atomicAdd(&g_done_count, 1u);
        if (prev == (unsigned)(gridDim.x - 1)) {
            double mean = g_loss_sum / (double)NELEM;
            float m = (float)mean;
            out[loss_idx] = __fadd_rn(__fmul_rn(m, 0.25f), m); // beta*commit + embed
            g_loss_sum   = 0.0;       // reset for next graph replay
            g_done_count = 0u;
        }
    }
}

extern "C" void kernel_launch(void* const* d_in, const int* in_sizes, int n_in,
                              void* d_out, int out_size) {
    const float* lat = (const float*)d_in[0];
    const float* w   = (const float*)d_in[1];
    float* out = (float*)d_out;

    const int smem_bytes = KCODES * DDIM * 4 + KCODES * 4 + (BLOCK / 32) * 8;
    cudaFuncSetAttribute(vq_kernel,
                         cudaFuncAttributeMaxDynamicSharedMemorySize, smem_bytes);

    vq_kernel<<<GRID, BLOCK, smem_bytes>>>(lat, w, out, out_size - 1);
}

// round 17
// speedup vs baseline: 1.5385x; 1.5385x over previous
#include <cuda_runtime.h>
#include <cstdint>

// VQ-VAE vector quantizer for GB300 — register-tiled GEMM structure,
// fma.rn.f32x2 with lanes = ADJACENT CODE PAIRS (pair-interleaved codebook
// in smem), pixel operand duplicated once per d and reused across 4 pairs.
// latents: [B=32, D=64, H=64, W=64] fp32, emb_weight: [K=512, D=64] fp32.
//
// Evidence: R7 proved FFMA2 is double-rate (2 MACs per rt-2 slot) and that
// per-FMA smem operand feeds are the limiter. Issue audit of the code-dup
// variant: 41 issue/32 fma-cyc (PACK2 = 2 MOVs). This layout: 29/32 -> fma-bound.
//
// Precision (rel_err 0.0 in R3/R7 with this chain):
//   sumw_k, sumf: unfused fl(x*x) chains, ascending d
//   s: ONE sequential FMA chain per (pixel, code), ascending d (f32x2 IEEE/lane)
//   dist = fl( fl(sumf + sumw) - fl(2*s) ); argmin strict-<, first-index ties
//   q_st = fl( f + fl(q - f) )

#define KCODES 512
#define NPAIR  256            // code pairs
#define DDIM   64
#define HW     4096
#define NPIX   131072
#define BLOCK  256
#define PXB    128            // pixels per block
#define NELEM  8388608
#define GRID   (NPIX / PXB)   // 1024 blocks
#define PSTRIDE 130           // floats per pair-row (128 data + 2 pad) -> no bank conflicts

__device__ double   g_loss_sum   = 0.0;
__device__ unsigned g_done_count = 0u;

#define PACK2(r, lo, hi) \
    asm("mov.b64 %0, {%1, %2};" : "=l"(r) : "r"(lo), "r"(hi))
#define UNPACK2(lo, hi, r) \
    asm("mov.b64 {%0, %1}, %2;" : "=r"(lo), "=r"(hi) : "l"(r))
#define FMA2(acc, a, b) \
    asm("fma.rn.f32x2 %0, %1, %2, %3;" : "=l"(acc) : "l"(a), "l"(b), "l"(acc))

// smem layout (floats):
//   scf   : pair-interleaved codebook, NPAIR*PSTRIDE   = 33280
//           pair kp, dim d: (w[2kp][d], w[2kp+1][d]) at scf[kp*130 + 2d (+1)]
//   spf   : pixel tile, 64 d-rows x 128 px             =  8192
//   ssumw : KCODES                                     =   512
//   ssumf : PXB                                        =   128
//   sbi   : PXB ints                                   =   128
//   sred  : 8 doubles                                  =    16
#define OFF_SPF   (NPAIR * PSTRIDE)
#define OFF_SUMW  (OFF_SPF + DDIM * PXB)
#define OFF_SUMF  (OFF_SUMW + KCODES)
#define OFF_SBI   (OFF_SUMF + PXB)
#define OFF_SRED  (OFF_SBI + PXB)
#define SMEM_FLOATS (OFF_SRED + 16)

__global__ void __launch_bounds__(BLOCK, 1) vq_kernel(
    const float* __restrict__ lat,
    const float* __restrict__ w,
    float* __restrict__ out,
    int loss_idx)
{
    extern __shared__ float smf[];
    float*  scf   = smf;
    float*  spf   = smf + OFF_SPF;
    float*  ssumw = smf + OFF_SUMW;
    float*  ssumf = smf + OFF_SUMF;
    int*    sbi   = reinterpret_cast<int*>(smf + OFF_SBI);
    double* sred  = reinterpret_cast<double*>(smf + OFF_SRED);

    const int tid = threadIdx.x;
    const int n0  = blockIdx.x * PXB;
    const int b   = n0 >> 12;
    const int hw0 = n0 & (HW - 1);
    const float* latb = lat + (size_t)b * (DDIM * HW) + hw0;

    // ---- stage pair-interleaved codebook + pixel tile ----
    for (int i = tid; i < KCODES * DDIM; i += BLOCK) {
        int k = i >> 6, d = i & 63;
        scf[(k >> 1) * PSTRIDE + 2 * d + (k & 1)] = w[i];
    }
    for (int i = tid; i < PXB * DDIM; i += BLOCK) {
        int px = i & (PXB - 1), d = i >> 7;
        spf[d * PXB + px] = latb[(size_t)d * HW + px];
    }
    __syncthreads();

    // ---- sumw (2 codes/thread), sumf (threads 0..127), reference rounding ----
#pragma unroll
    for (int c = 0; c < KCODES / BLOCK; ++c) {
        int k = tid + c * BLOCK;
        const float* wr = scf + (k >> 1) * PSTRIDE + (k & 1);
        float acc = 0.0f;
#pragma unroll
        for (int d = 0; d < DDIM; ++d) {
            float v = wr[2 * d];
            acc = __fadd_rn(acc, __fmul_rn(v, v));     // unfused, ascending d
        }
        ssumw[k] = acc;
    }
    if (tid < PXB) {
        float acc = 0.0f;
#pragma unroll
        for (int d = 0; d < DDIM; ++d) {
            float v = spf[d * PXB + tid];
            acc = __fadd_rn(acc, __fmul_rn(v, v));     // unfused, ascending d
        }
        ssumf[tid] = acc;
    }
    __syncthreads();

    // ---- main loop: thread (row,col): pixels 4row..4row+3  x  4 code-pairs/tile
    const int row = tid >> 3;          // 0..31
    const int col = tid & 7;           // 0..7
    const float4* sp4 = reinterpret_cast<const float4*>(spf);   // [d][32 groups of 4 px]

    float myf[4];
#pragma unroll
    for (int p = 0; p < 4; ++p) myf[p] = ssumf[4 * row + p];

    float best[4];
    int   bi[4];
#pragma unroll
    for (int p = 0; p < 4; ++p) { best[p] = 3.4e38f; bi[p] = 0; }

#pragma unroll 1
    for (int tile = 0; tile < 8; ++tile) {             // 32 pairs (64 codes) per tile
        const int pbase = tile * 32;
        const float* pp[4];
#pragma unroll
        for (int jp = 0; jp < 4; ++jp)
            pp[jp] = scf + (size_t)(pbase + col + 8 * jp) * PSTRIDE;

        uint64_t acc[4][4];                            // [px][pair]
#pragma unroll
        for (int p = 0; p < 4; ++p)
#pragma unroll
            for (int jp = 0; jp < 4; ++jp) PACK2(acc[p][jp], 0u, 0u);

#pragma unroll 8
        for (int d = 0; d < DDIM; ++d) {
            float4 pix = sp4[d * 32 + row];            // 4 pixels, 1 LDS.128 wavefront
            uint64_t pd[4];
            uint32_t x;
            x = __float_as_uint(pix.x); PACK2(pd[0], x, x);
            x = __float_as_uint(pix.y); PACK2(pd[1], x, x);
            x = __float_as_uint(pix.z); PACK2(pd[2], x, x);
            x = __float_as_uint(pix.w); PACK2(pd[3], x, x);
#pragma unroll
            for (int jp = 0; jp < 4; ++jp) {
                uint64_t wp = *reinterpret_cast<const uint64_t*>(pp[jp] + 2 * d); // LDS.64
                FMA2(acc[0][jp], pd[0], wp);
                FMA2(acc[1][jp], pd[1], wp);
                FMA2(acc[2][jp], pd[2], wp);
                FMA2(acc[3][jp], pd[3], wp);
            }
        }

#pragma unroll
        for (int jp = 0; jp < 4; ++jp) {               // ascending pair within thread
            const int k0  = 2 * (pbase + col + 8 * jp);
            const float sw0 = ssumw[k0];
            const float sw1 = ssumw[k0 + 1];
#pragma unroll
            for (int p = 0; p < 4; ++p) {
                uint32_t lo, hi;
                UNPACK2(lo, hi, acc[p][jp]);
                float d0 = __fsub_rn(__fadd_rn(myf[p], sw0), __fmul_rn(2.0f, __uint_as_float(lo)));
                float d1 = __fsub_rn(__fadd_rn(myf[p], sw1), __fmul_rn(2.0f, __uint_as_float(hi)));
                if (d0 < best[p]) { best[p] = d0; bi[p] = k0; }      // even code first
                if (d1 < best[p]) { best[p] = d1; bi[p] = k0 + 1; }  // then odd: asc. k
            }
        }
    }

    // ---- argmin across the 8 code-columns (lanes 8r..8r+7): lexicographic min ----
#pragma unroll
    for (int off = 1; off < 8; off <<= 1) {
#pragma unroll
        for (int p = 0; p < 4; ++p) {
            float ob = __shfl_xor_sync(0xFFFFFFFFu, best[p], off);
            int   oi = __shfl_xor_sync(0xFFFFFFFFu, bi[p],   off);
            if (ob < best[p] || (ob == best[p] && oi < bi[p])) {
                best[p] = ob; bi[p] = oi;
            }
        }
    }
    if (col == 0) {
#pragma unroll
        for (int p = 0; p < 4; ++p) sbi[4 * row + p] = bi[p];
    }
    __syncthreads();

    // ---- output + loss: thread t -> pixel t&127, d half t>>7 ----
    double lloss = 0.0;
    {
        const int px    = tid & (PXB - 1);
        const int dbase = (tid >> 7) * 32;
        const int kwin  = sbi[px];
        float* op = out + (size_t)b * (DDIM * HW) + hw0 + px;
        const float* q = scf + (size_t)(kwin >> 1) * PSTRIDE + (kwin & 1);
#pragma unroll
        for (int dd = 0; dd < 32; ++dd) {
            int d = dbase + dd;
            float fd   = spf[d * PXB + px];
            float diff = __fsub_rn(q[2 * d], fd);
            op[(size_t)d * HW] = __fadd_rn(fd, diff);   // fl(lat + fl(q - lat))
            lloss += (double)diff * (double)diff;
        }
    }

    // ---- loss reduction -> one atomicAdd per block ----
#pragma unroll
    for (int off = 16; off > 0; off >>= 1)
        lloss += __shfl_down_sync(0xFFFFFFFFu, lloss, off);
    if ((tid & 31) == 0) sred[tid >> 5] = lloss;
    __syncthreads();

    // ---- last-block finalize ----
    if (tid == 0) {
        double t = 0.0;
#pragma unroll
        for (int i = 0; i < BLOCK / 32; ++i) t += sred[i];
        atomicAdd(&g_loss_sum, t);
        __threadfence();
        unsigned prev = atomicAdd(&g_done_count, 1u);
        if (prev == (unsigned)(gridDim.x - 1)) {
            double mean = g_loss_sum / (double)NELEM;
            float m = (float)mean;
            out[loss_idx] = __fadd_rn(__fmul_rn(m, 0.25f), m); // beta*commit + embed
            g_loss_sum   = 0.0;
            g_done_count = 0u;
        }
    }
}

extern "C" void kernel_launch(void* const* d_in, const int* in_sizes, int n_in,
                              void* d_out, int out_size) {
    const float* lat = (const float*)d_in[0];
    const float* w   = (const float*)d_in[1];
    float* out = (float*)d_out;

    const int smem_bytes = SMEM_FLOATS * 4;     // ~169 KB
    cudaFuncSetAttribute(vq_kernel,
                         cudaFuncAttributeMaxDynamicSharedMemorySize, smem_bytes);

    vq_kernel<<<GRID, BLOCK, smem_bytes>>>(lat, w, out, out_size - 1);
}